// round 9
// baseline (speedup 1.0000x reference)
#include <cuda_runtime.h>
#include <cstdint>

// FilterBankConstructorND — R9:
//  * tetra + ones_vec in __constant__ (removes ~36 broadcast LDG wavefronts
//    per warp from l1tex — half the pipe's work in R8)
//  * BLK=256, input staging buffer unioned into s_fb (smem 35KB -> 29.7KB)
//  * TMA bulk stores, early rot store, wait_group.read
//
// Inputs (metadata order):
//   d_in[0]: spheres         (K, 5)  float32, K = 1048576
//   d_in[1]: ones_vec        (3,)    float32
//   d_in[2]: tetra_rotations (4,3,3) float32
// Output: concat of rotations_0 (K,3,3) then filter_banks (4K,5,1), float32.

#ifndef FB_EPS
#define FB_EPS 1e-12f
#endif

#define BLK 256

__constant__ float c_tetra[36];
__constant__ float c_ones[3];

__device__ __forceinline__ unsigned smem_u32(const void* p) {
    return (unsigned)__cvta_generic_to_shared(p);
}

__global__ __launch_bounds__(BLK)
void fb_kernel(const float* __restrict__ spheres,
               float* __restrict__ out_rot,   // (K,3,3)
               float* __restrict__ out_fb,    // (4K,5) = 20 floats per sphere
               int K)
{
    __shared__ __align__(128) float s_rot[9 * BLK];   //  9216 B, output-linear
    __shared__ __align__(128) float s_fb[20 * BLK];   // 20480 B, output-linear
    // input staging is unioned into the front of s_fb: all reads of it happen
    // before the barrier that precedes any fb write.
    float* s_in = s_fb;                               //  5120 B overlay

    const int tid = threadIdx.x;
    const size_t base = (size_t)blockIdx.x * BLK;   // first sphere of this block

    // ---- coalesced block load: BLK spheres x 5 floats ----
    const float* gin = spheres + base * 5;
#pragma unroll
    for (int i = 0; i < 5; i++)
        s_in[tid + i * BLK] = gin[tid + i * BLK];

    // ---- constants (LDC, off l1tex; overlaps LDG latency) ----
    float q0 = c_ones[0], q1 = c_ones[1], q2 = c_ones[2];
    {
        float qn = rsqrtf(q0 * q0 + q1 * q1 + q2 * q2);
        q0 *= qn; q1 *= qn; q2 *= qn;
    }
    __syncthreads();   // sync1: input staged

    const float s0 = s_in[tid * 5 + 0];
    const float s1 = s_in[tid * 5 + 1];
    const float s2 = s_in[tid * 5 + 2];
    const float s3 = s_in[tid * 5 + 3];
    const float s4 = s_in[tid * 5 + 4];

    // centers = s[:3] / (s[4] + eps); normalize
    float inv = __frcp_rn(s4 + FB_EPS);
    float c0 = s0 * inv, c1 = s1 * inv, c2 = s2 * inv;
    float cn = rsqrtf(c0 * c0 + c1 * c1 + c2 * c2);
    float p0 = c0 * cn, p1 = c1 * cn, p2 = c2 * cn;

    // u = p + q
    float u0 = p0 + q0, u1 = p1 + q1, u2 = p2 + q2;
    float uu = u0 * u0 + u1 * u1 + u2 * u2;
    float two_iuu = 2.0f / uu;
    float qq = q0 * q0 + q1 * q1 + q2 * q2;   // ~1, mirror reference arithmetic
    float two_iqq = 2.0f / qq;

    // H_q = I - (2/qq) q q^T
    float Hq00 = 1.0f - two_iqq * q0 * q0;
    float Hq01 =       -two_iqq * q0 * q1;
    float Hq02 =       -two_iqq * q0 * q2;
    float Hq11 = 1.0f - two_iqq * q1 * q1;
    float Hq12 =       -two_iqq * q1 * q2;
    float Hq22 = 1.0f - two_iqq * q2 * q2;

    // h = H_q u
    float qu = q0 * u0 + q1 * u1 + q2 * u2;
    float h0 = u0 - two_iqq * q0 * qu;
    float h1 = u1 - two_iqq * q1 * qu;
    float h2 = u2 - two_iqq * q2 * qu;

    // R0 = H_q - (2/uu) (H_q u) u^T
    float R00 = Hq00 - two_iuu * h0 * u0;
    float R01 = Hq01 - two_iuu * h0 * u1;
    float R02 = Hq02 - two_iuu * h0 * u2;
    float R10 = Hq01 - two_iuu * h1 * u0;
    float R11 = Hq11 - two_iuu * h1 * u1;
    float R12 = Hq12 - two_iuu * h1 * u2;
    float R20 = Hq02 - two_iuu * h2 * u0;
    float R21 = Hq12 - two_iuu * h2 * u1;
    float R22 = Hq22 - two_iuu * h2 * u2;

    // stage rotations output-linear (stride 9, conflict-free STS)
    {
        float* r = s_rot + tid * 9;
        r[0] = R00; r[1] = R01; r[2] = R02;
        r[3] = R10; r[4] = R11; r[5] = R12;
        r[6] = R20; r[7] = R21; r[8] = R22;
    }
    __syncthreads();   // sync2: rot staged; also fences s_in reads vs fb writes

    // ---- early TMA: rot store streams while fb is computed ----
    if (tid == 0) {
        asm volatile("fence.proxy.async.shared::cta;" ::: "memory");
        uint64_t g_rot = (uint64_t)(out_rot + base * 9);
        asm volatile(
            "cp.async.bulk.global.shared::cta.bulk_group [%0], [%1], %2;"
            :: "l"(g_rot), "r"(smem_u32(s_rot)), "n"(9 * BLK * 4) : "memory");
        asm volatile("cp.async.bulk.commit_group;" ::: "memory");
    }

    // rotated top = R0 @ s[:3]
    float t0 = R00 * s0 + R01 * s1 + R02 * s2;
    float t1 = R10 * s0 + R11 * s1 + R12 * s2;
    float t2 = R20 * s0 + R21 * s1 + R22 * s2;

    // fb_m = R0^T (T_m @ t); stage output-linear at stride 20 via 5x STS.128
    {
        float f[4][3];
#pragma unroll
        for (int m = 0; m < 4; m++) {
            const float* T = c_tetra + 9 * m;        // LDC broadcasts
            float w0 = T[0] * t0 + T[1] * t1 + T[2] * t2;
            float w1 = T[3] * t0 + T[4] * t1 + T[5] * t2;
            float w2 = T[6] * t0 + T[7] * t1 + T[8] * t2;
            f[m][0] = R00 * w0 + R10 * w1 + R20 * w2;
            f[m][1] = R01 * w0 + R11 * w1 + R21 * w2;
            f[m][2] = R02 * w0 + R12 * w1 + R22 * w2;
        }
        float4* fb4 = reinterpret_cast<float4*>(s_fb + tid * 20);
        fb4[0] = make_float4(f[0][0], f[0][1], f[0][2], s3);
        fb4[1] = make_float4(s4,      f[1][0], f[1][1], f[1][2]);
        fb4[2] = make_float4(s3,      s4,      f[2][0], f[2][1]);
        fb4[3] = make_float4(f[2][2], s3,      s4,      f[3][0]);
        fb4[4] = make_float4(f[3][1], f[3][2], s3,      s4);
    }
    __syncthreads();   // sync3: fb staged

    // ---- fb TMA store + release: wait only until smem has been READ ----
    if (tid == 0) {
        asm volatile("fence.proxy.async.shared::cta;" ::: "memory");
        uint64_t g_fb = (uint64_t)(out_fb + base * 20);
        asm volatile(
            "cp.async.bulk.global.shared::cta.bulk_group [%0], [%1], %2;"
            :: "l"(g_fb), "r"(smem_u32(s_fb)), "n"(20 * BLK * 4) : "memory");
        asm volatile("cp.async.bulk.commit_group;" ::: "memory");
        asm volatile("cp.async.bulk.wait_group.read 0;" ::: "memory");
    }
}

extern "C" void kernel_launch(void* const* d_in, const int* in_sizes, int n_in,
                              void* d_out, int out_size)
{
    const float* spheres = (const float*)d_in[0];
    const float* ones_v  = (const float*)d_in[1];
    const float* tetra   = (const float*)d_in[2];

    // broadcast constants -> __constant__ (D2D async copies, graph-capturable)
    cudaMemcpyToSymbolAsync(c_ones,  ones_v, 3  * sizeof(float), 0,
                            cudaMemcpyDeviceToDevice, 0);
    cudaMemcpyToSymbolAsync(c_tetra, tetra,  36 * sizeof(float), 0,
                            cudaMemcpyDeviceToDevice, 0);

    int K = in_sizes[0] / 5;                   // spheres is (K, 5)
    float* out_rot = (float*)d_out;            // (K, 3, 3)
    float* out_fb  = out_rot + 9 * (size_t)K;  // (4K, 5)

    int blocks = K / BLK;                      // K = 2^20, exact multiple
    fb_kernel<<<blocks, BLK>>>(spheres, out_rot, out_fb, K);
}

// round 10
// speedup vs baseline: 1.0729x; 1.0729x over previous
#include <cuda_runtime.h>
#include <cstdint>

// FilterBankConstructorND — R10:
//  * NO per-launch memcpy nodes (R9's memcpyToSymbol cost ~3.5us/replay in
//    the captured graph, more than the kernel win). tetra is cooperatively
//    staged to smem and read as 3x LDS.128 broadcasts per matrix.
//  * BLK=256, input staging overlaid on s_fb, early rot TMA store,
//    fb TMA store with wait_group.read.
//
// Inputs (metadata order):
//   d_in[0]: spheres         (K, 5)  float32, K = 1048576
//   d_in[1]: ones_vec        (3,)    float32
//   d_in[2]: tetra_rotations (4,3,3) float32
// Output: concat of rotations_0 (K,3,3) then filter_banks (4K,5,1), float32.

#ifndef FB_EPS
#define FB_EPS 1e-12f
#endif

#define BLK 256

__device__ __forceinline__ unsigned smem_u32(const void* p) {
    return (unsigned)__cvta_generic_to_shared(p);
}

__global__ __launch_bounds__(BLK)
void fb_kernel(const float* __restrict__ spheres,
               const float* __restrict__ ones_vec,
               const float* __restrict__ tetra,
               float* __restrict__ out_rot,   // (K,3,3)
               float* __restrict__ out_fb,    // (4K,5) = 20 floats per sphere
               int K)
{
    __shared__ __align__(128) float s_rot[9 * BLK];   //  9216 B, output-linear
    __shared__ __align__(128) float s_fb[20 * BLK];   // 20480 B, output-linear
    __shared__ __align__(16)  float s_tet[4 * 12];    //   192 B, 12 floats/matrix
    // input staging overlaid on the front of s_fb: all reads of it happen
    // before the barrier (sync2) that precedes any fb write.
    float* s_in = s_fb;                               //  5120 B overlay

    const int tid = threadIdx.x;
    const size_t base = (size_t)blockIdx.x * BLK;   // first sphere of this block

    // ---- coalesced block load: BLK spheres x 5 floats ----
    const float* gin = spheres + base * 5;
#pragma unroll
    for (int i = 0; i < 5; i++)
        s_in[tid + i * BLK] = gin[tid + i * BLK];

    // ---- cooperative tetra staging (padded: matrix m at s_tet[12m .. 12m+8]) ----
    if (tid < 36)
        s_tet[(tid / 9) * 12 + (tid % 9)] = tetra[tid];

    // ---- ones_vec: 3 broadcast LDG (L1-resident) ----
    float q0 = __ldg(ones_vec + 0);
    float q1 = __ldg(ones_vec + 1);
    float q2 = __ldg(ones_vec + 2);
    {
        float qn = rsqrtf(q0 * q0 + q1 * q1 + q2 * q2);
        q0 *= qn; q1 *= qn; q2 *= qn;
    }
    __syncthreads();   // sync1: input + tetra staged

    const float s0 = s_in[tid * 5 + 0];
    const float s1 = s_in[tid * 5 + 1];
    const float s2 = s_in[tid * 5 + 2];
    const float s3 = s_in[tid * 5 + 3];
    const float s4 = s_in[tid * 5 + 4];

    // centers = s[:3] / (s[4] + eps); normalize
    float inv = __frcp_rn(s4 + FB_EPS);
    float c0 = s0 * inv, c1 = s1 * inv, c2 = s2 * inv;
    float cn = rsqrtf(c0 * c0 + c1 * c1 + c2 * c2);
    float p0 = c0 * cn, p1 = c1 * cn, p2 = c2 * cn;

    // u = p + q
    float u0 = p0 + q0, u1 = p1 + q1, u2 = p2 + q2;
    float uu = u0 * u0 + u1 * u1 + u2 * u2;
    float two_iuu = 2.0f / uu;
    float qq = q0 * q0 + q1 * q1 + q2 * q2;   // ~1, mirror reference arithmetic
    float two_iqq = 2.0f / qq;

    // H_q = I - (2/qq) q q^T
    float Hq00 = 1.0f - two_iqq * q0 * q0;
    float Hq01 =       -two_iqq * q0 * q1;
    float Hq02 =       -two_iqq * q0 * q2;
    float Hq11 = 1.0f - two_iqq * q1 * q1;
    float Hq12 =       -two_iqq * q1 * q2;
    float Hq22 = 1.0f - two_iqq * q2 * q2;

    // h = H_q u
    float qu = q0 * u0 + q1 * u1 + q2 * u2;
    float h0 = u0 - two_iqq * q0 * qu;
    float h1 = u1 - two_iqq * q1 * qu;
    float h2 = u2 - two_iqq * q2 * qu;

    // R0 = H_q - (2/uu) (H_q u) u^T
    float R00 = Hq00 - two_iuu * h0 * u0;
    float R01 = Hq01 - two_iuu * h0 * u1;
    float R02 = Hq02 - two_iuu * h0 * u2;
    float R10 = Hq01 - two_iuu * h1 * u0;
    float R11 = Hq11 - two_iuu * h1 * u1;
    float R12 = Hq12 - two_iuu * h1 * u2;
    float R20 = Hq02 - two_iuu * h2 * u0;
    float R21 = Hq12 - two_iuu * h2 * u1;
    float R22 = Hq22 - two_iuu * h2 * u2;

    // stage rotations output-linear (stride 9, conflict-free STS)
    {
        float* r = s_rot + tid * 9;
        r[0] = R00; r[1] = R01; r[2] = R02;
        r[3] = R10; r[4] = R11; r[5] = R12;
        r[6] = R20; r[7] = R21; r[8] = R22;
    }
    __syncthreads();   // sync2: rot staged; fences s_in reads vs fb writes

    // ---- early TMA: rot store streams while fb is computed ----
    if (tid == 0) {
        asm volatile("fence.proxy.async.shared::cta;" ::: "memory");
        uint64_t g_rot = (uint64_t)(out_rot + base * 9);
        asm volatile(
            "cp.async.bulk.global.shared::cta.bulk_group [%0], [%1], %2;"
            :: "l"(g_rot), "r"(smem_u32(s_rot)), "n"(9 * BLK * 4) : "memory");
        asm volatile("cp.async.bulk.commit_group;" ::: "memory");
    }

    // rotated top = R0 @ s[:3]
    float t0 = R00 * s0 + R01 * s1 + R02 * s2;
    float t1 = R10 * s0 + R11 * s1 + R12 * s2;
    float t2 = R20 * s0 + R21 * s1 + R22 * s2;

    // fb_m = R0^T (T_m @ t); T via 3x LDS.128 broadcasts per matrix
    {
        float f[4][3];
        const float4* tet4 = reinterpret_cast<const float4*>(s_tet);
#pragma unroll
        for (int m = 0; m < 4; m++) {
            float4 Ta = tet4[m * 3 + 0];   // T00 T01 T02 T10
            float4 Tb = tet4[m * 3 + 1];   // T11 T12 T20 T21
            float4 Tc = tet4[m * 3 + 2];   // T22 pad pad pad
            float w0 = Ta.x * t0 + Ta.y * t1 + Ta.z * t2;
            float w1 = Ta.w * t0 + Tb.x * t1 + Tb.y * t2;
            float w2 = Tb.z * t0 + Tb.w * t1 + Tc.x * t2;
            f[m][0] = R00 * w0 + R10 * w1 + R20 * w2;
            f[m][1] = R01 * w0 + R11 * w1 + R21 * w2;
            f[m][2] = R02 * w0 + R12 * w1 + R22 * w2;
        }
        float4* fb4 = reinterpret_cast<float4*>(s_fb + tid * 20);
        fb4[0] = make_float4(f[0][0], f[0][1], f[0][2], s3);
        fb4[1] = make_float4(s4,      f[1][0], f[1][1], f[1][2]);
        fb4[2] = make_float4(s3,      s4,      f[2][0], f[2][1]);
        fb4[3] = make_float4(f[2][2], s3,      s4,      f[3][0]);
        fb4[4] = make_float4(f[3][1], f[3][2], s3,      s4);
    }
    __syncthreads();   // sync3: fb staged

    // ---- fb TMA store + release: wait only until smem has been READ ----
    if (tid == 0) {
        asm volatile("fence.proxy.async.shared::cta;" ::: "memory");
        uint64_t g_fb = (uint64_t)(out_fb + base * 20);
        asm volatile(
            "cp.async.bulk.global.shared::cta.bulk_group [%0], [%1], %2;"
            :: "l"(g_fb), "r"(smem_u32(s_fb)), "n"(20 * BLK * 4) : "memory");
        asm volatile("cp.async.bulk.commit_group;" ::: "memory");
        asm volatile("cp.async.bulk.wait_group.read 0;" ::: "memory");
    }
}

extern "C" void kernel_launch(void* const* d_in, const int* in_sizes, int n_in,
                              void* d_out, int out_size)
{
    const float* spheres = (const float*)d_in[0];
    const float* ones_v  = (const float*)d_in[1];
    const float* tetra   = (const float*)d_in[2];

    int K = in_sizes[0] / 5;                   // spheres is (K, 5)
    float* out_rot = (float*)d_out;            // (K, 3, 3)
    float* out_fb  = out_rot + 9 * (size_t)K;  // (4K, 5)

    int blocks = K / BLK;                      // K = 2^20, exact multiple
    fb_kernel<<<blocks, BLK>>>(spheres, ones_v, tetra, out_rot, out_fb, K);
}

// round 12
// speedup vs baseline: 1.0767x; 1.0035x over previous
#include <cuda_runtime.h>
#include <cstdint>

// FilterBankConstructorND — R11: warp-autonomous pipeline.
// Each warp owns 32 spheres end-to-end (load -> compute -> stage -> its OWN
// per-warp TMA bulk stores). Only one block barrier (tetra staging at start);
// everything else is __syncwarp. Removes the block-wide barrier/TMA
// serialization that pinned R10 at occ 45% / issue 43%.
//
// Inputs (metadata order):
//   d_in[0]: spheres         (K, 5)  float32, K = 1048576
//   d_in[1]: ones_vec        (3,)    float32
//   d_in[2]: tetra_rotations (4,3,3) float32
// Output: concat of rotations_0 (K,3,3) then filter_banks (4K,5,1), float32.

#ifndef FB_EPS
#define FB_EPS 1e-12f
#endif

#define BLK 256

__device__ __forceinline__ unsigned smem_u32(const void* p) {
    return (unsigned)__cvta_generic_to_shared(p);
}

__global__ __launch_bounds__(BLK)
void fb_kernel(const float* __restrict__ spheres,
               const float* __restrict__ ones_vec,
               const float* __restrict__ tetra,
               float* __restrict__ out_rot,   // (K,3,3)
               float* __restrict__ out_fb,    // (4K,5) = 20 floats per sphere
               int K)
{
    __shared__ __align__(128) float s_rot[9 * BLK];   //  9216 B, per-warp slices
    __shared__ __align__(128) float s_fb[20 * BLK];   // 20480 B, per-warp slices
    __shared__ __align__(16)  float s_tet[4 * 12];    //   192 B, 12 floats/matrix

    const int tid  = threadIdx.x;
    const int wid  = tid >> 5;
    const int lane = tid & 31;
    const size_t wbase = (size_t)blockIdx.x * BLK + (size_t)(wid << 5);

    // per-warp smem slices
    float* s_rotw = s_rot + wid * (9 * 32);    // 1152 B
    float* s_fbw  = s_fb  + wid * (20 * 32);   // 2560 B
    // warp-local input staging overlaid on front of this warp's fb slice
    float* s_inw  = s_fbw;                     //  640 B

    // ---- warp-local coalesced input load: 32 spheres x 5 floats ----
    const float* gin = spheres + wbase * 5;
#pragma unroll
    for (int i = 0; i < 5; i++)
        s_inw[lane + 32 * i] = gin[lane + 32 * i];

    // ---- tetra staging (padded 12/matrix) — the ONLY block-wide sync ----
    if (tid < 36)
        s_tet[(tid / 9) * 12 + (tid % 9)] = tetra[tid];

    // ---- ones_vec (broadcast LDG, overlaps latency) ----
    float q0 = __ldg(ones_vec + 0);
    float q1 = __ldg(ones_vec + 1);
    float q2 = __ldg(ones_vec + 2);
    {
        float qn = rsqrtf(q0 * q0 + q1 * q1 + q2 * q2);
        q0 *= qn; q1 *= qn; q2 *= qn;
    }
    __syncthreads();   // tetra visible to all warps; also orders input staging

    const float s0 = s_inw[lane * 5 + 0];
    const float s1 = s_inw[lane * 5 + 1];
    const float s2 = s_inw[lane * 5 + 2];
    const float s3 = s_inw[lane * 5 + 3];
    const float s4 = s_inw[lane * 5 + 4];
    __syncwarp();      // all lanes' s_in reads complete before fb overwrites

    // centers = s[:3] / (s[4] + eps); normalize
    float inv = __frcp_rn(s4 + FB_EPS);
    float c0 = s0 * inv, c1 = s1 * inv, c2 = s2 * inv;
    float cn = rsqrtf(c0 * c0 + c1 * c1 + c2 * c2);
    float p0 = c0 * cn, p1 = c1 * cn, p2 = c2 * cn;

    // u = p + q
    float u0 = p0 + q0, u1 = p1 + q1, u2 = p2 + q2;
    float uu = u0 * u0 + u1 * u1 + u2 * u2;
    float two_iuu = 2.0f / uu;
    float qq = q0 * q0 + q1 * q1 + q2 * q2;   // ~1, mirror reference arithmetic
    float two_iqq = 2.0f / qq;

    // H_q = I - (2/qq) q q^T
    float Hq00 = 1.0f - two_iqq * q0 * q0;
    float Hq01 =       -two_iqq * q0 * q1;
    float Hq02 =       -two_iqq * q0 * q2;
    float Hq11 = 1.0f - two_iqq * q1 * q1;
    float Hq12 =       -two_iqq * q1 * q2;
    float Hq22 = 1.0f - two_iqq * q2 * q2;

    // h = H_q u
    float qu = q0 * u0 + q1 * u1 + q2 * u2;
    float h0 = u0 - two_iqq * q0 * qu;
    float h1 = u1 - two_iqq * q1 * qu;
    float h2 = u2 - two_iqq * q2 * qu;

    // R0 = H_q - (2/uu) (H_q u) u^T
    float R00 = Hq00 - two_iuu * h0 * u0;
    float R01 = Hq01 - two_iuu * h0 * u1;
    float R02 = Hq02 - two_iuu * h0 * u2;
    float R10 = Hq01 - two_iuu * h1 * u0;
    float R11 = Hq11 - two_iuu * h1 * u1;
    float R12 = Hq12 - two_iuu * h1 * u2;
    float R20 = Hq02 - two_iuu * h2 * u0;
    float R21 = Hq12 - two_iuu * h2 * u1;
    float R22 = Hq22 - two_iuu * h2 * u2;

    // stage rotations output-linear (stride 9, conflict-free STS)
    {
        float* r = s_rotw + lane * 9;
        r[0] = R00; r[1] = R01; r[2] = R02;
        r[3] = R10; r[4] = R11; r[5] = R12;
        r[6] = R20; r[7] = R21; r[8] = R22;
    }
    __syncwarp();

    // ---- per-warp early TMA: rot store streams while fb is computed ----
    if (lane == 0) {
        asm volatile("fence.proxy.async.shared::cta;" ::: "memory");
        uint64_t g_rot = (uint64_t)(out_rot + wbase * 9);
        asm volatile(
            "cp.async.bulk.global.shared::cta.bulk_group [%0], [%1], %2;"
            :: "l"(g_rot), "r"(smem_u32(s_rotw)), "n"(9 * 32 * 4) : "memory");
        asm volatile("cp.async.bulk.commit_group;" ::: "memory");
    }

    // rotated top = R0 @ s[:3]
    float t0 = R00 * s0 + R01 * s1 + R02 * s2;
    float t1 = R10 * s0 + R11 * s1 + R12 * s2;
    float t2 = R20 * s0 + R21 * s1 + R22 * s2;

    // fb_m = R0^T (T_m @ t); T via 3x LDS.128 broadcasts per matrix
    {
        float f[4][3];
        const float4* tet4 = reinterpret_cast<const float4*>(s_tet);
#pragma unroll
        for (int m = 0; m < 4; m++) {
            float4 Ta = tet4[m * 3 + 0];   // T00 T01 T02 T10
            float4 Tb = tet4[m * 3 + 1];   // T11 T12 T20 T21
            float4 Tc = tet4[m * 3 + 2];   // T22 pad pad pad
            float w0 = Ta.x * t0 + Ta.y * t1 + Ta.z * t2;
            float w1 = Ta.w * t0 + Tb.x * t1 + Tb.y * t2;
            float w2 = Tb.z * t0 + Tb.w * t1 + Tc.x * t2;
            f[m][0] = R00 * w0 + R10 * w1 + R20 * w2;
            f[m][1] = R01 * w0 + R11 * w1 + R21 * w2;
            f[m][2] = R02 * w0 + R12 * w1 + R22 * w2;
        }
        float4* fb4 = reinterpret_cast<float4*>(s_fbw + lane * 20);
        fb4[0] = make_float4(f[0][0], f[0][1], f[0][2], s3);
        fb4[1] = make_float4(s4,      f[1][0], f[1][1], f[1][2]);
        fb4[2] = make_float4(s3,      s4,      f[2][0], f[2][1]);
        fb4[3] = make_float4(f[2][2], s3,      s4,      f[3][0]);
        fb4[4] = make_float4(f[3][1], f[3][2], s3,      s4);
    }
    __syncwarp();

    // ---- per-warp fb TMA store + release (wait only for smem READ) ----
    if (lane == 0) {
        asm volatile("fence.proxy.async.shared::cta;" ::: "memory");
        uint64_t g_fb = (uint64_t)(out_fb + wbase * 20);
        asm volatile(
            "cp.async.bulk.global.shared::cta.bulk_group [%0], [%1], %2;"
            :: "l"(g_fb), "r"(smem_u32(s_fbw)), "n"(20 * 32 * 4) : "memory");
        asm volatile("cp.async.bulk.commit_group;" ::: "memory");
        asm volatile("cp.async.bulk.wait_group.read 0;" ::: "memory");
    }
}

extern "C" void kernel_launch(void* const* d_in, const int* in_sizes, int n_in,
                              void* d_out, int out_size)
{
    const float* spheres = (const float*)d_in[0];
    const float* ones_v  = (const float*)d_in[1];
    const float* tetra   = (const float*)d_in[2];

    int K = in_sizes[0] / 5;                   // spheres is (K, 5)
    float* out_rot = (float*)d_out;            // (K, 3, 3)
    float* out_fb  = out_rot + 9 * (size_t)K;  // (4K, 5)

    int blocks = K / BLK;                      // K = 2^20, exact multiple
    fb_kernel<<<blocks, BLK>>>(spheres, ones_v, tetra, out_rot, out_fb, K);
}